// round 16
// baseline (speedup 1.0000x reference)
#include <cuda_runtime.h>
#include <cuda_bf16.h>
#include <cuda_fp16.h>
#include <math.h>

// Problem constants
#define QS 256
#define LS 2048
#define NB 64
#define SS 26
#define NPOST (NB * LS * QS)     // 33,554,432
#define EM_ROWS 64

// fb geometry: 256 threads = 8 warps (R13 layout, reordered issue)
//   warp w owns columns [32w, 32w+32)
//   lane: g = lane>>3 (row group), li = lane&7; cc = 32w + 4*li; rows [64g, 64g+64)
//   row pairs (per thread, 32 pairs = 64 rows):
//     pairs  0..19 : fp32 regs   (80 u64 = 160 regs)
//     pairs 20..25 : fp32 shared (24 u64 = 48 u32)
//     pairs 26..31 : fp16 shared (24 u32)
#define MYROW_PITCH 76           // 72 payload u32 + 4 pad; 304B = 19*16B, conflict-free
#define MYROW_U32 (256 * MYROW_PITCH)    // 19456 u32 = 76 KB

// Skewed p buffer: 4 chunks of 64 floats, 16B pad between chunks (R9 proven).
#define PD_F 272
#define PSLOT(s) ((s) + 4 * ((s) >> 6))

// Renorm block length
#define RBS 32

// ---------------------------------------------------------------------------
// Device scratch
// ---------------------------------------------------------------------------
__device__ float g_expA[QS * QS];     // exp(log_A)  [j][i]
__device__ float g_expAT[QS * QS];    // transpose
__device__ float g_expB[QS * 32];
__device__ float g_pi[QS];
__device__ float g_emit[NPOST];       // [b][l][q]
__device__ float g_alpha[NPOST];
__device__ float g_beta[NPOST];
__device__ float g_Ca[NB * LS];
__device__ float g_Cb[NB * LS];
__device__ float g_loglik[NB];

// ---------------------------------------------------------------------------
// f32x2 helpers
// ---------------------------------------------------------------------------
__device__ __forceinline__ unsigned long long pk(float x, float y) {
    unsigned long long r;
    asm("mov.b64 %0, {%1,%2};" : "=l"(r) : "f"(x), "f"(y));
    return r;
}
__device__ __forceinline__ void ffma2(unsigned long long& c,
                                      unsigned long long a,
                                      unsigned long long b) {
    asm("fma.rn.f32x2 %0, %1, %2, %0;" : "+l"(c) : "l"(a), "l"(b));
}
__device__ __forceinline__ unsigned long long mul2(unsigned long long a,
                                                   unsigned long long b) {
    unsigned long long r;
    asm("mul.rn.f32x2 %0, %1, %2;" : "=l"(r) : "l"(a), "l"(b));
    return r;
}
__device__ __forceinline__ float2 unpk(unsigned long long u) {
    float lo, hi;
    asm("mov.b64 {%0,%1}, %2;" : "=f"(lo), "=f"(hi) : "l"(u));
    return make_float2(lo, hi);
}
// fp16x2 word -> packed f32x2 operand (widening)
__device__ __forceinline__ unsigned long long h2u64(unsigned int w) {
    __half2 h = *reinterpret_cast<const __half2*>(&w);
    float2 f = __half22float2(h);
    return pk(f.x, f.y);
}
__device__ __forceinline__ unsigned int pack_h16(float a, float b) {
    __half2 h = __floats2half2_rn(a, b);
    return *reinterpret_cast<unsigned int*>(&h);
}

// ---------------------------------------------------------------------------
// Kernel 0: exp() of parameters
// ---------------------------------------------------------------------------
__global__ void precompute_kernel(const float* __restrict__ log_A,
                                  const float* __restrict__ log_pi,
                                  const float* __restrict__ log_B) {
    int idx = blockIdx.x * 256 + threadIdx.x;
    if (blockIdx.x < 256) {
        float v = expf(log_A[idx]);
        g_expA[idx] = v;
        int j = idx >> 8, i = idx & 255;
        g_expAT[i * QS + j] = v;
    } else if (blockIdx.x < 282) {
        int k = idx - 65536;
        if (k < QS * SS) {
            int q = k / SS, s = k - q * SS;
            g_expB[q * 32 + s] = expf(log_B[k]);
        }
    } else {
        if (threadIdx.x < QS) g_pi[threadIdx.x] = expf(log_pi[threadIdx.x]);
    }
}

// ---------------------------------------------------------------------------
// Kernel 1: emission GEMM
// ---------------------------------------------------------------------------
__global__ void __launch_bounds__(256) emission_kernel(const float* __restrict__ inputs) {
    __shared__ float in_sh[EM_ROWS][SS];
    int tid = threadIdx.x;
    int row0 = blockIdx.x * EM_ROWS;

    for (int i = tid; i < EM_ROWS * SS; i += 256)
        in_sh[i / SS][i % SS] = inputs[row0 * SS + i];
    float eb[SS];
#pragma unroll
    for (int s = 0; s < SS; s++) eb[s] = g_expB[tid * 32 + s];
    __syncthreads();

#pragma unroll 4
    for (int r = 0; r < EM_ROWS; r++) {
        float acc = 0.0f;
#pragma unroll
        for (int s = 0; s < SS; s++) acc = fmaf(in_sh[r][s], eb[s], acc);
        g_emit[(size_t)(row0 + r) * QS + tid] = acc;
    }
}

// ---------------------------------------------------------------------------
// ncu alignment marker (keeps fb in ncu's profiled launch slot)
// ---------------------------------------------------------------------------
__global__ void fb_marker_kernel() {}

// ---------------------------------------------------------------------------
// Kernel 2: scaled forward/backward; 32-step renorm blocks; branch-free
// plain steps; e prefetched one step ahead (load-bearing!).
// MATVEC issue order: ALL shared-A loads first, register FFMA last ->
// memory latency hidden under register-only math; step tail is load-free.
// Block 0..63 forward chain b; block 64..127 backward chain b-64.
// ---------------------------------------------------------------------------
extern __shared__ unsigned int shu[];

#define SH_MYROW  (shu)
#define SH_P(bf)  ((float*)(shu + MYROW_U32) + (bf) * PD_F)
#define SH_RED    ((float*)(shu + MYROW_U32) + 2 * PD_F)

// matvec + reduce: full column sums m0..m3 for this thread's 4 columns
#define MATVEC_REDUCE()                                                        \
    const ulonglong2* pdv = (const ulonglong2*)(SH_P(cur) + pd_base);          \
    unsigned long long acc0, acc1, acc2, acc3;                                 \
    /* --- shared fp32 pairs 20,21 (init accumulators) --- */                  \
    {                                                                          \
        ulonglong2 q = pdv[10];                                                \
        const ulonglong2* mr = (const ulonglong2*)(myrow64);                   \
        ulonglong2 wa0 = mr[0];                                                \
        ulonglong2 wa1 = mr[1];                                                \
        ulonglong2 wb0 = mr[2];                                                \
        ulonglong2 wb1 = mr[3];                                                \
        acc0 = mul2(wa0.x, q.x);                                               \
        acc1 = mul2(wa0.y, q.x);                                               \
        acc2 = mul2(wa1.x, q.x);                                               \
        acc3 = mul2(wa1.y, q.x);                                               \
        ffma2(acc0, wb0.x, q.y);                                               \
        ffma2(acc1, wb0.y, q.y);                                               \
        ffma2(acc2, wb1.x, q.y);                                               \
        ffma2(acc3, wb1.y, q.y);                                               \
    }                                                                          \
    /* --- shared fp32 pairs 22..25 --- */                                     \
    _Pragma("unroll")                                                          \
    for (int k = 1; k < 3; k++) {                                              \
        ulonglong2 q = pdv[10 + k];                                            \
        const ulonglong2* mr = (const ulonglong2*)(myrow64 + 8 * k);           \
        ulonglong2 wa0 = mr[0];                                                \
        ulonglong2 wa1 = mr[1];                                                \
        ulonglong2 wb0 = mr[2];                                                \
        ulonglong2 wb1 = mr[3];                                                \
        ffma2(acc0, wa0.x, q.x);                                               \
        ffma2(acc1, wa0.y, q.x);                                               \
        ffma2(acc2, wa1.x, q.x);                                               \
        ffma2(acc3, wa1.y, q.x);                                               \
        ffma2(acc0, wb0.x, q.y);                                               \
        ffma2(acc1, wb0.y, q.y);                                               \
        ffma2(acc2, wb1.x, q.y);                                               \
        ffma2(acc3, wb1.y, q.y);                                               \
    }                                                                          \
    /* --- shared fp16 pairs 26..31 --- */                                     \
    _Pragma("unroll")                                                          \
    for (int k = 0; k < 3; k++) {                                              \
        ulonglong2 q = pdv[13 + k];                                            \
        uint4 wa = mH4[2 * k];                                                 \
        uint4 wb = mH4[2 * k + 1];                                             \
        ffma2(acc0, h2u64(wa.x), q.x);                                         \
        ffma2(acc1, h2u64(wa.y), q.x);                                         \
        ffma2(acc2, h2u64(wa.z), q.x);                                         \
        ffma2(acc3, h2u64(wa.w), q.x);                                         \
        ffma2(acc0, h2u64(wb.x), q.y);                                         \
        ffma2(acc1, h2u64(wb.y), q.y);                                         \
        ffma2(acc2, h2u64(wb.z), q.y);                                         \
        ffma2(acc3, h2u64(wb.w), q.y);                                         \
    }                                                                          \
    /* --- register fp32 pairs 0..19 (pure-register tail) --- */               \
    _Pragma("unroll")                                                          \
    for (int k = 0; k < 10; k++) {                                             \
        ulonglong2 q = pdv[k];                                                 \
        ffma2(acc0, Areg[8 * k + 0], q.x);                                     \
        ffma2(acc1, Areg[8 * k + 1], q.x);                                     \
        ffma2(acc2, Areg[8 * k + 2], q.x);                                     \
        ffma2(acc3, Areg[8 * k + 3], q.x);                                     \
        ffma2(acc0, Areg[8 * k + 4], q.y);                                     \
        ffma2(acc1, Areg[8 * k + 5], q.y);                                     \
        ffma2(acc2, Areg[8 * k + 6], q.y);                                     \
        ffma2(acc3, Areg[8 * k + 7], q.y);                                     \
    }                                                                          \
    /* horizontal add, then 2 float butterfly stages (8 SHFL total) */         \
    float2 s0 = unpk(acc0), s1 = unpk(acc1), s2 = unpk(acc2), s3 = unpk(acc3); \
    float m0 = s0.x + s0.y, m1 = s1.x + s1.y, m2 = s2.x + s2.y, m3 = s3.x + s3.y; \
    m0 += __shfl_xor_sync(FULL, m0, 8);                                        \
    m1 += __shfl_xor_sync(FULL, m1, 8);                                        \
    m2 += __shfl_xor_sync(FULL, m2, 8);                                        \
    m3 += __shfl_xor_sync(FULL, m3, 8);                                        \
    m0 += __shfl_xor_sync(FULL, m0, 16);                                       \
    m1 += __shfl_xor_sync(FULL, m1, 16);                                       \
    m2 += __shfl_xor_sync(FULL, m2, 16);                                       \
    m3 += __shfl_xor_sync(FULL, m3, 16);

__global__ void __launch_bounds__(256, 1) fb_kernel() {
    int tid  = threadIdx.x;
    int w    = tid >> 5;
    int lane = tid & 31;
    int g    = lane >> 3;
    int li   = lane & 7;
    int cc   = 32 * w + 4 * li;          // my 4 columns
    int r0   = 64 * g;                   // my 64 rows

    int bx = blockIdx.x;
    bool fwd = (bx < NB);
    int b = fwd ? bx : bx - NB;
    const float* Ag = fwd ? g_expA : g_expAT;

    // pairs 0..19 -> fp32 row-pair regs
    unsigned long long Areg[80];
#pragma unroll
    for (int j2 = 0; j2 < 20; j2++) {
        const float* ra = Ag + (r0 + 2 * j2) * QS + cc;
        const float* rb = ra + QS;
#pragma unroll
        for (int c = 0; c < 4; c++)
            Areg[j2 * 4 + c] = pk(ra[c], rb[c]);
    }
    // pairs 20..25 -> fp32 in private shared row (u64[24])
    unsigned long long* myrow64 =
        (unsigned long long*)(SH_MYROW + tid * MYROW_PITCH);
#pragma unroll
    for (int p = 0; p < 6; p++) {
        const float* ra = Ag + (r0 + 40 + 2 * p) * QS + cc;
        const float* rb = ra + QS;
#pragma unroll
        for (int c = 0; c < 4; c++)
            myrow64[p * 4 + c] = pk(ra[c], rb[c]);
    }
    // pairs 26..31 -> fp16 (u32[24] at word offset 48)
    unsigned int* myrowH = SH_MYROW + tid * MYROW_PITCH + 48;
#pragma unroll
    for (int p = 0; p < 6; p++) {
        const float* ra = Ag + (r0 + 52 + 2 * p) * QS + cc;
        const float* rb = ra + QS;
#pragma unroll
        for (int c = 0; c < 4; c++)
            myrowH[p * 4 + c] = pack_h16(ra[c], rb[c]);
    }
    const uint4* mH4 = (const uint4*)myrowH;

    const float* em_b = g_emit + (size_t)b * LS * QS;
    float* st_b = (fwd ? g_alpha : g_beta) + (size_t)b * LS * QS;
    float* C_b  = (fwd ? g_Ca : g_Cb) + b * LS;

    // --- boundary init (skewed p slots) ---
    {
        int s = tid;
        if (fwd) {
            float v = g_pi[s] * em_b[s];
            st_b[s] = v;
            SH_P(0)[PSLOT(s)] = v;
            if (s == 0) C_b[0] = 0.0f;
        } else {
            st_b[(size_t)(LS - 1) * QS + s] = 1.0f;
            SH_P(0)[PSLOT(s)] = em_b[(size_t)(LS - 1) * QS + s];
            if (s == 0) C_b[LS - 1] = 0.0f;
        }
    }
    __syncthreads();

    double C = 0.0;
    float Cf = 0.0f;
    int cur = 0;
    const unsigned FULL = 0xffffffffu;
    int pd_base = 68 * g;                 // skewed chunk base for my row-group
    int pslot_w = PSLOT(cc);              // skewed write slot for my columns

    if (fwd) {
        int t = 1;
        float4 e_cur = *(const float4*)(em_b + (size_t)t * QS + cc);
        for (int blk = 0; blk < LS / RBS; blk++) {
            int n = (blk == 0) ? (RBS - 1) : RBS;
            if (tid < n) C_b[t + tid] = Cf;
#pragma unroll 1
            for (int i = 0; i < n - 1; i++) {
                int tp = t + 1;
                float4 e_nxt = *(const float4*)(em_b + (size_t)tp * QS + cc);
                MATVEC_REDUCE();
                float4 stv = make_float4(m0 * e_cur.x, m1 * e_cur.y,
                                         m2 * e_cur.z, m3 * e_cur.w);
                if (g == 0)
                    *(float4*)(SH_P(cur ^ 1) + pslot_w) = stv;
                __syncthreads();
                if (g == 0)
                    *(float4*)(st_b + (size_t)t * QS + cc) = stv;
                cur ^= 1;
                e_cur = e_nxt;
                t++;
            }
            // renorm step
            {
                int tp = (t + 1 < LS) ? (t + 1) : (LS - 1);
                float4 e_nxt = *(const float4*)(em_b + (size_t)tp * QS + cc);
                MATVEC_REDUCE();
                float4 stv = make_float4(m0 * e_cur.x, m1 * e_cur.y,
                                         m2 * e_cur.z, m3 * e_cur.w);
                float ls = (stv.x + stv.y) + (stv.z + stv.w);
                ls += __shfl_xor_sync(FULL, ls, 1);
                ls += __shfl_xor_sync(FULL, ls, 2);
                ls += __shfl_xor_sync(FULL, ls, 4);
                if (lane == 0) SH_RED[w] = ls;
                __syncthreads();
                float s = 0.0f;
#pragma unroll
                for (int ww = 0; ww < 8; ww++) s += SH_RED[ww];
                if (t == LS - 1 && tid == 0)
                    g_loglik[b] = (float)(C + (double)logf(s));
                C += (double)logf(s);
                Cf = (float)C;
                float inv = 1.0f / s;
                float4 pv = make_float4(stv.x * inv, stv.y * inv,
                                        stv.z * inv, stv.w * inv);
                if (g == 0)
                    *(float4*)(SH_P(cur ^ 1) + pslot_w) = pv;
                __syncthreads();
                if (g == 0)
                    *(float4*)(st_b + (size_t)t * QS + cc) = stv;
                cur ^= 1;
                e_cur = e_nxt;
                t++;
            }
        }
    } else {
        int t = LS - 2;
        float4 e_cur = *(const float4*)(em_b + (size_t)t * QS + cc);
        for (int blk = 0; blk < LS / RBS; blk++) {
            int n = (blk == 0) ? (RBS - 1) : RBS;
            if (tid < n) C_b[t - tid] = Cf;
#pragma unroll 1
            for (int i = 0; i < n - 1; i++) {
                int tp = t - 1;
                float4 e_nxt = *(const float4*)(em_b + (size_t)tp * QS + cc);
                MATVEC_REDUCE();
                float4 stv = make_float4(m0, m1, m2, m3);
                float4 pv = make_float4(m0 * e_cur.x, m1 * e_cur.y,
                                        m2 * e_cur.z, m3 * e_cur.w);
                if (g == 0)
                    *(float4*)(SH_P(cur ^ 1) + pslot_w) = pv;
                __syncthreads();
                if (g == 0)
                    *(float4*)(st_b + (size_t)t * QS + cc) = stv;
                cur ^= 1;
                e_cur = e_nxt;
                t--;
            }
            // renorm step
            {
                int tp = (t - 1 >= 0) ? (t - 1) : 0;
                float4 e_nxt = *(const float4*)(em_b + (size_t)tp * QS + cc);
                MATVEC_REDUCE();
                float4 stv = make_float4(m0, m1, m2, m3);
                float ls = (m0 + m1) + (m2 + m3);
                ls += __shfl_xor_sync(FULL, ls, 1);
                ls += __shfl_xor_sync(FULL, ls, 2);
                ls += __shfl_xor_sync(FULL, ls, 4);
                if (lane == 0) SH_RED[w] = ls;
                __syncthreads();
                float s = 0.0f;
#pragma unroll
                for (int ww = 0; ww < 8; ww++) s += SH_RED[ww];
                C += (double)logf(s);
                Cf = (float)C;
                float inv = 1.0f / s;
                float4 pv = make_float4(m0 * inv * e_cur.x, m1 * inv * e_cur.y,
                                        m2 * inv * e_cur.z, m3 * inv * e_cur.w);
                if (g == 0)
                    *(float4*)(SH_P(cur ^ 1) + pslot_w) = pv;
                __syncthreads();
                if (g == 0)
                    *(float4*)(st_b + (size_t)t * QS + cc) = stv;
                cur ^= 1;
                e_cur = e_nxt;
                t--;
            }
        }
    }
}

// ---------------------------------------------------------------------------
// Kernel 3: posterior + loglik
// ---------------------------------------------------------------------------
__global__ void __launch_bounds__(256) posterior_kernel(float* __restrict__ out, int out_size) {
    int i4 = blockIdx.x * 256 + threadIdx.x;
    int idx = i4 << 2;
    int bt = idx >> 8;
    int b  = bt >> 11;
    float4 a  = *(const float4*)(g_alpha + idx);
    float4 be = *(const float4*)(g_beta + idx);
    float c = g_Ca[bt] + g_Cb[bt] - g_loglik[b];
    float4 o;
    o.x = logf(a.x * be.x) + c;
    o.y = logf(a.y * be.y) + c;
    o.z = logf(a.z * be.z) + c;
    o.w = logf(a.w * be.w) + c;
    *(float4*)(out + idx) = o;
    if (i4 < NB && out_size >= NPOST + NB)
        out[NPOST + i4] = g_loglik[i4];
}

// ---------------------------------------------------------------------------
// Launch
// ---------------------------------------------------------------------------
extern "C" void kernel_launch(void* const* d_in, const int* in_sizes, int n_in,
                              void* d_out, int out_size) {
    const float* inputs = (const float*)d_in[0];   // (1,64,2048,26)
    const float* log_A  = (const float*)d_in[1];   // (1,256,256)
    const float* log_pi = (const float*)d_in[2];   // (1,256)
    const float* log_B  = (const float*)d_in[3];   // (1,256,26)
    float* out = (float*)d_out;

    precompute_kernel<<<283, 256>>>(log_A, log_pi, log_B);
    emission_kernel<<<(NB * LS) / EM_ROWS, 256>>>(inputs);
    fb_marker_kernel<<<1, 32>>>();                 // keeps fb in ncu's -s 5 slot

    int smem = (MYROW_U32 + 2 * PD_F + 16 + 16) * (int)sizeof(unsigned int);
    cudaFuncSetAttribute(fb_kernel, cudaFuncAttributeMaxDynamicSharedMemorySize, smem);
    fb_kernel<<<2 * NB, 256, smem>>>();

    posterior_kernel<<<NPOST / 1024, 256>>>(out, out_size);
}

// round 17
// speedup vs baseline: 1.5929x; 1.5929x over previous
#include <cuda_runtime.h>
#include <cuda_bf16.h>
#include <cuda_fp16.h>
#include <math.h>

// Problem constants
#define QS 256
#define LS 2048
#define NB 64
#define SS 26
#define NPOST (NB * LS * QS)     // 33,554,432
#define EM_ROWS 64

// fb geometry: 256 threads = 8 warps (R13 layout — proven best)
//   warp w owns columns [32w, 32w+32)
//   lane: g = lane>>3 (row group), li = lane&7; cc = 32w + 4*li; rows [64g, 64g+64)
//   row pairs (per thread, 32 pairs = 64 rows):
//     pairs  0..19 : fp32 regs   (80 u64 = 160 regs)
//     pairs 20..25 : fp32 shared (24 u64 = 48 u32)
//     pairs 26..31 : fp16 shared (24 u32)
#define MYROW_PITCH 76           // 72 payload u32 + 4 pad; 304B = 19*16B, conflict-free
#define MYROW_U32 (256 * MYROW_PITCH)    // 19456 u32 = 76 KB

// Skewed p buffer: 4 chunks of 64 floats, 16B pad between chunks (R9 proven).
#define PD_F 272
#define PSLOT(s) ((s) + 4 * ((s) >> 6))

// Renorm block length (sum drift ~0.5^64 ≈ 5e-20/block — safely fp32-normal)
#define RBS 64

// ---------------------------------------------------------------------------
// Device scratch
// ---------------------------------------------------------------------------
__device__ float g_expA[QS * QS];     // exp(log_A)  [j][i]
__device__ float g_expAT[QS * QS];    // transpose
__device__ float g_expB[QS * 32];
__device__ float g_pi[QS];
__device__ float g_emit[NPOST];       // [b][l][q]
__device__ float g_alpha[NPOST];
__device__ float g_beta[NPOST];
__device__ float g_Ca[NB * LS];
__device__ float g_Cb[NB * LS];
__device__ float g_loglik[NB];

// ---------------------------------------------------------------------------
// f32x2 helpers
// ---------------------------------------------------------------------------
__device__ __forceinline__ unsigned long long pk(float x, float y) {
    unsigned long long r;
    asm("mov.b64 %0, {%1,%2};" : "=l"(r) : "f"(x), "f"(y));
    return r;
}
__device__ __forceinline__ void ffma2(unsigned long long& c,
                                      unsigned long long a,
                                      unsigned long long b) {
    asm("fma.rn.f32x2 %0, %1, %2, %0;" : "+l"(c) : "l"(a), "l"(b));
}
__device__ __forceinline__ unsigned long long mul2(unsigned long long a,
                                                   unsigned long long b) {
    unsigned long long r;
    asm("mul.rn.f32x2 %0, %1, %2;" : "=l"(r) : "l"(a), "l"(b));
    return r;
}
__device__ __forceinline__ float2 unpk(unsigned long long u) {
    float lo, hi;
    asm("mov.b64 {%0,%1}, %2;" : "=f"(lo), "=f"(hi) : "l"(u));
    return make_float2(lo, hi);
}
// fp16x2 word -> packed f32x2 operand (widening)
__device__ __forceinline__ unsigned long long h2u64(unsigned int w) {
    __half2 h = *reinterpret_cast<const __half2*>(&w);
    float2 f = __half22float2(h);
    return pk(f.x, f.y);
}
__device__ __forceinline__ unsigned int pack_h16(float a, float b) {
    __half2 h = __floats2half2_rn(a, b);
    return *reinterpret_cast<unsigned int*>(&h);
}

// ---------------------------------------------------------------------------
// Kernel 0: exp() of parameters
// ---------------------------------------------------------------------------
__global__ void precompute_kernel(const float* __restrict__ log_A,
                                  const float* __restrict__ log_pi,
                                  const float* __restrict__ log_B) {
    int idx = blockIdx.x * 256 + threadIdx.x;
    if (blockIdx.x < 256) {
        float v = expf(log_A[idx]);
        g_expA[idx] = v;
        int j = idx >> 8, i = idx & 255;
        g_expAT[i * QS + j] = v;
    } else if (blockIdx.x < 282) {
        int k = idx - 65536;
        if (k < QS * SS) {
            int q = k / SS, s = k - q * SS;
            g_expB[q * 32 + s] = expf(log_B[k]);
        }
    } else {
        if (threadIdx.x < QS) g_pi[threadIdx.x] = expf(log_pi[threadIdx.x]);
    }
}

// ---------------------------------------------------------------------------
// Kernel 1: emission GEMM — expB staged through shared (coalesced LDG)
// ---------------------------------------------------------------------------
__global__ void __launch_bounds__(256) emission_kernel(const float* __restrict__ inputs) {
    __shared__ float in_sh[EM_ROWS][SS];
    __shared__ float eb_sh[256 * 27];    // pad 27: gcd(27,32)=1 -> conflict-free
    int tid = threadIdx.x;
    int row0 = blockIdx.x * EM_ROWS;

    // coalesced copy of expB (8192 floats) into shared, unpadding 32->27
    for (int i = tid; i < QS * 32; i += 256) {
        int q = i >> 5, s = i & 31;
        if (s < SS) eb_sh[q * 27 + s] = g_expB[i];
    }
    for (int i = tid; i < EM_ROWS * SS; i += 256)
        in_sh[i / SS][i % SS] = inputs[row0 * SS + i];
    __syncthreads();

    float eb[SS];
#pragma unroll
    for (int s = 0; s < SS; s++) eb[s] = eb_sh[tid * 27 + s];

#pragma unroll 4
    for (int r = 0; r < EM_ROWS; r++) {
        float acc = 0.0f;
#pragma unroll
        for (int s = 0; s < SS; s++) acc = fmaf(in_sh[r][s], eb[s], acc);
        g_emit[(size_t)(row0 + r) * QS + tid] = acc;
    }
}

// ---------------------------------------------------------------------------
// ncu alignment marker (keeps fb in ncu's profiled launch slot)
// ---------------------------------------------------------------------------
__global__ void fb_marker_kernel() {}

// ---------------------------------------------------------------------------
// Kernel 2: scaled forward/backward; 64-step renorm blocks; branch-free
// plain steps; e prefetched one step ahead (load-bearing!). R13 hot loop.
// Block 0..63 forward chain b; block 64..127 backward chain b-64.
// ---------------------------------------------------------------------------
extern __shared__ unsigned int shu[];

#define SH_MYROW  (shu)
#define SH_P(bf)  ((float*)(shu + MYROW_U32) + (bf) * PD_F)
#define SH_RED    ((float*)(shu + MYROW_U32) + 2 * PD_F)

// matvec + reduce: full column sums m0..m3 for this thread's 4 columns
// (R13 issue order — proven; do not reorder)
#define MATVEC_REDUCE()                                                        \
    const ulonglong2* pdv = (const ulonglong2*)(SH_P(cur) + pd_base);          \
    unsigned long long acc0, acc1, acc2, acc3;                                 \
    {                                                                          \
        ulonglong2 q = pdv[0];                                                 \
        acc0 = mul2(Areg[0], q.x);                                             \
        acc1 = mul2(Areg[1], q.x);                                             \
        acc2 = mul2(Areg[2], q.x);                                             \
        acc3 = mul2(Areg[3], q.x);                                             \
        ffma2(acc0, Areg[4], q.y);                                             \
        ffma2(acc1, Areg[5], q.y);                                             \
        ffma2(acc2, Areg[6], q.y);                                             \
        ffma2(acc3, Areg[7], q.y);                                             \
    }                                                                          \
    _Pragma("unroll")                                                          \
    for (int k = 1; k < 10; k++) {         /* pairs 2k,2k+1 (fp32 regs) */     \
        ulonglong2 q = pdv[k];                                                 \
        ffma2(acc0, Areg[8 * k + 0], q.x);                                     \
        ffma2(acc1, Areg[8 * k + 1], q.x);                                     \
        ffma2(acc2, Areg[8 * k + 2], q.x);                                     \
        ffma2(acc3, Areg[8 * k + 3], q.x);                                     \
        ffma2(acc0, Areg[8 * k + 4], q.y);                                     \
        ffma2(acc1, Areg[8 * k + 5], q.y);                                     \
        ffma2(acc2, Areg[8 * k + 6], q.y);                                     \
        ffma2(acc3, Areg[8 * k + 7], q.y);                                     \
    }                                                                          \
    _Pragma("unroll")                                                          \
    for (int k = 0; k < 3; k++) {          /* pairs 20..25 (fp32 shared) */    \
        ulonglong2 q = pdv[10 + k];                                            \
        const ulonglong2* mr = (const ulonglong2*)(myrow64 + 8 * k);           \
        ulonglong2 wa0 = mr[0];                                                \
        ulonglong2 wa1 = mr[1];                                                \
        ulonglong2 wb0 = mr[2];                                                \
        ulonglong2 wb1 = mr[3];                                                \
        ffma2(acc0, wa0.x, q.x);                                               \
        ffma2(acc1, wa0.y, q.x);                                               \
        ffma2(acc2, wa1.x, q.x);                                               \
        ffma2(acc3, wa1.y, q.x);                                               \
        ffma2(acc0, wb0.x, q.y);                                               \
        ffma2(acc1, wb0.y, q.y);                                               \
        ffma2(acc2, wb1.x, q.y);                                               \
        ffma2(acc3, wb1.y, q.y);                                               \
    }                                                                          \
    _Pragma("unroll")                                                          \
    for (int k = 0; k < 3; k++) {          /* pairs 26..31 (fp16 shared) */    \
        ulonglong2 q = pdv[13 + k];                                            \
        uint4 wa = mH4[2 * k];                                                 \
        uint4 wb = mH4[2 * k + 1];                                             \
        ffma2(acc0, h2u64(wa.x), q.x);                                         \
        ffma2(acc1, h2u64(wa.y), q.x);                                         \
        ffma2(acc2, h2u64(wa.z), q.x);                                         \
        ffma2(acc3, h2u64(wa.w), q.x);                                         \
        ffma2(acc0, h2u64(wb.x), q.y);                                         \
        ffma2(acc1, h2u64(wb.y), q.y);                                         \
        ffma2(acc2, h2u64(wb.z), q.y);                                         \
        ffma2(acc3, h2u64(wb.w), q.y);                                         \
    }                                                                          \
    /* horizontal add, then 2 float butterfly stages (8 SHFL total) */         \
    float2 s0 = unpk(acc0), s1 = unpk(acc1), s2 = unpk(acc2), s3 = unpk(acc3); \
    float m0 = s0.x + s0.y, m1 = s1.x + s1.y, m2 = s2.x + s2.y, m3 = s3.x + s3.y; \
    m0 += __shfl_xor_sync(FULL, m0, 8);                                        \
    m1 += __shfl_xor_sync(FULL, m1, 8);                                        \
    m2 += __shfl_xor_sync(FULL, m2, 8);                                        \
    m3 += __shfl_xor_sync(FULL, m3, 8);                                        \
    m0 += __shfl_xor_sync(FULL, m0, 16);                                       \
    m1 += __shfl_xor_sync(FULL, m1, 16);                                       \
    m2 += __shfl_xor_sync(FULL, m2, 16);                                       \
    m3 += __shfl_xor_sync(FULL, m3, 16);

__global__ void __launch_bounds__(256, 1) fb_kernel() {
    int tid  = threadIdx.x;
    int w    = tid >> 5;
    int lane = tid & 31;
    int g    = lane >> 3;
    int li   = lane & 7;
    int cc   = 32 * w + 4 * li;          // my 4 columns
    int r0   = 64 * g;                   // my 64 rows

    int bx = blockIdx.x;
    bool fwd = (bx < NB);
    int b = fwd ? bx : bx - NB;
    const float* Ag = fwd ? g_expA : g_expAT;

    // pairs 0..19 -> fp32 row-pair regs
    unsigned long long Areg[80];
#pragma unroll
    for (int j2 = 0; j2 < 20; j2++) {
        const float* ra = Ag + (r0 + 2 * j2) * QS + cc;
        const float* rb = ra + QS;
#pragma unroll
        for (int c = 0; c < 4; c++)
            Areg[j2 * 4 + c] = pk(ra[c], rb[c]);
    }
    // pairs 20..25 -> fp32 in private shared row (u64[24])
    unsigned long long* myrow64 =
        (unsigned long long*)(SH_MYROW + tid * MYROW_PITCH);
#pragma unroll
    for (int p = 0; p < 6; p++) {
        const float* ra = Ag + (r0 + 40 + 2 * p) * QS + cc;
        const float* rb = ra + QS;
#pragma unroll
        for (int c = 0; c < 4; c++)
            myrow64[p * 4 + c] = pk(ra[c], rb[c]);
    }
    // pairs 26..31 -> fp16 (u32[24] at word offset 48)
    unsigned int* myrowH = SH_MYROW + tid * MYROW_PITCH + 48;
#pragma unroll
    for (int p = 0; p < 6; p++) {
        const float* ra = Ag + (r0 + 52 + 2 * p) * QS + cc;
        const float* rb = ra + QS;
#pragma unroll
        for (int c = 0; c < 4; c++)
            myrowH[p * 4 + c] = pack_h16(ra[c], rb[c]);
    }
    const uint4* mH4 = (const uint4*)myrowH;

    const float* em_b = g_emit + (size_t)b * LS * QS;
    float* st_b = (fwd ? g_alpha : g_beta) + (size_t)b * LS * QS;
    float* C_b  = (fwd ? g_Ca : g_Cb) + b * LS;

    // --- boundary init (skewed p slots) ---
    {
        int s = tid;
        if (fwd) {
            float v = g_pi[s] * em_b[s];
            st_b[s] = v;
            SH_P(0)[PSLOT(s)] = v;
            if (s == 0) C_b[0] = 0.0f;
        } else {
            st_b[(size_t)(LS - 1) * QS + s] = 1.0f;
            SH_P(0)[PSLOT(s)] = em_b[(size_t)(LS - 1) * QS + s];
            if (s == 0) C_b[LS - 1] = 0.0f;
        }
    }
    __syncthreads();

    double C = 0.0;
    float Cf = 0.0f;
    int cur = 0;
    const unsigned FULL = 0xffffffffu;
    int pd_base = 68 * g;                 // skewed chunk base for my row-group
    int pslot_w = PSLOT(cc);              // skewed write slot for my columns

    if (fwd) {
        int t = 1;
        float4 e_cur = *(const float4*)(em_b + (size_t)t * QS + cc);
        for (int blk = 0; blk < LS / RBS; blk++) {
            int n = (blk == 0) ? (RBS - 1) : RBS;
            if (tid < n) C_b[t + tid] = Cf;
#pragma unroll 1
            for (int i = 0; i < n - 1; i++) {
                int tp = t + 1;
                float4 e_nxt = *(const float4*)(em_b + (size_t)tp * QS + cc);
                MATVEC_REDUCE();
                float4 stv = make_float4(m0 * e_cur.x, m1 * e_cur.y,
                                         m2 * e_cur.z, m3 * e_cur.w);
                if (g == 0)
                    *(float4*)(SH_P(cur ^ 1) + pslot_w) = stv;
                __syncthreads();
                if (g == 0)
                    *(float4*)(st_b + (size_t)t * QS + cc) = stv;
                cur ^= 1;
                e_cur = e_nxt;
                t++;
            }
            // renorm step
            {
                int tp = (t + 1 < LS) ? (t + 1) : (LS - 1);
                float4 e_nxt = *(const float4*)(em_b + (size_t)tp * QS + cc);
                MATVEC_REDUCE();
                float4 stv = make_float4(m0 * e_cur.x, m1 * e_cur.y,
                                         m2 * e_cur.z, m3 * e_cur.w);
                float ls = (stv.x + stv.y) + (stv.z + stv.w);
                ls += __shfl_xor_sync(FULL, ls, 1);
                ls += __shfl_xor_sync(FULL, ls, 2);
                ls += __shfl_xor_sync(FULL, ls, 4);
                if (lane == 0) SH_RED[w] = ls;
                __syncthreads();
                float s = 0.0f;
#pragma unroll
                for (int ww = 0; ww < 8; ww++) s += SH_RED[ww];
                if (t == LS - 1 && tid == 0)
                    g_loglik[b] = (float)(C + (double)logf(s));
                C += (double)logf(s);
                Cf = (float)C;
                float inv = 1.0f / s;
                float4 pv = make_float4(stv.x * inv, stv.y * inv,
                                        stv.z * inv, stv.w * inv);
                if (g == 0)
                    *(float4*)(SH_P(cur ^ 1) + pslot_w) = pv;
                __syncthreads();
                if (g == 0)
                    *(float4*)(st_b + (size_t)t * QS + cc) = stv;
                cur ^= 1;
                e_cur = e_nxt;
                t++;
            }
        }
    } else {
        int t = LS - 2;
        float4 e_cur = *(const float4*)(em_b + (size_t)t * QS + cc);
        for (int blk = 0; blk < LS / RBS; blk++) {
            int n = (blk == 0) ? (RBS - 1) : RBS;
            if (tid < n) C_b[t - tid] = Cf;
#pragma unroll 1
            for (int i = 0; i < n - 1; i++) {
                int tp = t - 1;
                float4 e_nxt = *(const float4*)(em_b + (size_t)tp * QS + cc);
                MATVEC_REDUCE();
                float4 stv = make_float4(m0, m1, m2, m3);
                float4 pv = make_float4(m0 * e_cur.x, m1 * e_cur.y,
                                        m2 * e_cur.z, m3 * e_cur.w);
                if (g == 0)
                    *(float4*)(SH_P(cur ^ 1) + pslot_w) = pv;
                __syncthreads();
                if (g == 0)
                    *(float4*)(st_b + (size_t)t * QS + cc) = stv;
                cur ^= 1;
                e_cur = e_nxt;
                t--;
            }
            // renorm step
            {
                int tp = (t - 1 >= 0) ? (t - 1) : 0;
                float4 e_nxt = *(const float4*)(em_b + (size_t)tp * QS + cc);
                MATVEC_REDUCE();
                float4 stv = make_float4(m0, m1, m2, m3);
                float ls = (m0 + m1) + (m2 + m3);
                ls += __shfl_xor_sync(FULL, ls, 1);
                ls += __shfl_xor_sync(FULL, ls, 2);
                ls += __shfl_xor_sync(FULL, ls, 4);
                if (lane == 0) SH_RED[w] = ls;
                __syncthreads();
                float s = 0.0f;
#pragma unroll
                for (int ww = 0; ww < 8; ww++) s += SH_RED[ww];
                C += (double)logf(s);
                Cf = (float)C;
                float inv = 1.0f / s;
                float4 pv = make_float4(m0 * inv * e_cur.x, m1 * inv * e_cur.y,
                                        m2 * inv * e_cur.z, m3 * inv * e_cur.w);
                if (g == 0)
                    *(float4*)(SH_P(cur ^ 1) + pslot_w) = pv;
                __syncthreads();
                if (g == 0)
                    *(float4*)(st_b + (size_t)t * QS + cc) = stv;
                cur ^= 1;
                e_cur = e_nxt;
                t--;
            }
        }
    }
}

// ---------------------------------------------------------------------------
// Kernel 3: posterior + loglik
// ---------------------------------------------------------------------------
__global__ void __launch_bounds__(256) posterior_kernel(float* __restrict__ out, int out_size) {
    int i4 = blockIdx.x * 256 + threadIdx.x;
    int idx = i4 << 2;
    int bt = idx >> 8;
    int b  = bt >> 11;
    float4 a  = *(const float4*)(g_alpha + idx);
    float4 be = *(const float4*)(g_beta + idx);
    float c = g_Ca[bt] + g_Cb[bt] - g_loglik[b];
    float4 o;
    o.x = logf(a.x * be.x) + c;
    o.y = logf(a.y * be.y) + c;
    o.z = logf(a.z * be.z) + c;
    o.w = logf(a.w * be.w) + c;
    *(float4*)(out + idx) = o;
    if (i4 < NB && out_size >= NPOST + NB)
        out[NPOST + i4] = g_loglik[i4];
}

// ---------------------------------------------------------------------------
// Launch
// ---------------------------------------------------------------------------
extern "C" void kernel_launch(void* const* d_in, const int* in_sizes, int n_in,
                              void* d_out, int out_size) {
    const float* inputs = (const float*)d_in[0];   // (1,64,2048,26)
    const float* log_A  = (const float*)d_in[1];   // (1,256,256)
    const float* log_pi = (const float*)d_in[2];   // (1,256)
    const float* log_B  = (const float*)d_in[3];   // (1,256,26)
    float* out = (float*)d_out;

    precompute_kernel<<<283, 256>>>(log_A, log_pi, log_B);
    emission_kernel<<<(NB * LS) / EM_ROWS, 256>>>(inputs);
    fb_marker_kernel<<<1, 32>>>();                 // keeps fb in ncu's -s 5 slot

    int smem = (MYROW_U32 + 2 * PD_F + 16 + 16) * (int)sizeof(unsigned int);
    cudaFuncSetAttribute(fb_kernel, cudaFuncAttributeMaxDynamicSharedMemorySize, smem);
    fb_kernel<<<2 * NB, 256, smem>>>();

    posterior_kernel<<<NPOST / 1024, 256>>>(out, out_size);
}